// round 6
// baseline (speedup 1.0000x reference)
#include <cuda_runtime.h>
#include <cstdint>

#define B   8
#define C   512
#define K   19
#define HW  16384
#define INV_HW (1.0f / 16384.0f)

typedef unsigned long long u64;

// scratch (allocation-free rule: __device__ globals)
__device__ float g_cf[B * K * C];     // class_feat accumulator
__device__ float g_filt[B * K * C];   // per-sample dynamic filters

// ---- packed f32x2 helpers (sm_103a FFMA2 — not emitted by ptxas from C++) ----
__device__ __forceinline__ u64 pack2(float lo, float hi) {
    u64 r; asm("mov.b64 %0, {%1, %2};" : "=l"(r) : "f"(lo), "f"(hi)); return r;
}
__device__ __forceinline__ void fma2(u64& d, u64 a, u64 b) {
    asm("fma.rn.f32x2 %0, %1, %2, %0;" : "+l"(d) : "l"(a), "l"(b));
}
__device__ __forceinline__ float2 unpack2(u64 v) {
    float2 f; asm("mov.b64 {%0, %1}, %2;" : "=f"(f.x), "=f"(f.y) : "l"(v)); return f;
}
__device__ __forceinline__ float sigmoidf_(float z) {
    return 1.0f / (1.0f + __expf(-z));
}

// ---------------------------------------------------------------------------
// Kernel 0: zero the class_feat accumulator
// ---------------------------------------------------------------------------
__global__ void zero_cf_kernel() {
    int i = blockIdx.x * blockDim.x + threadIdx.x;
    if (i < B * K * C) g_cf[i] = 0.0f;
}

// ---------------------------------------------------------------------------
// Kernel 1: fused mask_conv + sigmoid + masked pooling   (FFMA2)
//   grid = (32, 8), block = 256, tile T=512 pixels, 2 adjacent px / thread
//   smem: sWm[K*C] floats (38912B) + sMask[K*T] (38912B); padded to 120KB to
//   force 1 block/SM so live tiles (~74MB) stay L2-resident across phases.
// ---------------------------------------------------------------------------
#define MP_TPB 256
#define MP_T   512
#define MP_NT  (HW / MP_T)   // 32
#define MP_SMEM (120 * 1024)

extern __shared__ float smp[];

__global__ __launch_bounds__(MP_TPB) void mask_pool_kernel(
    const float* __restrict__ x,
    const float* __restrict__ Wm,
    const float* __restrict__ bm)
{
    float* sWm   = smp;            // [K][C]
    float* sMask = smp + K * C;    // [K][MP_T]

    const int tid = threadIdx.x;
    const int b   = blockIdx.y;
    const int p0  = blockIdx.x * MP_T;
    const float* __restrict__ xb = x + (size_t)b * C * HW;

    for (int i = tid; i < K * C; i += MP_TPB) sWm[i] = Wm[i];
    __syncthreads();
    const u64* __restrict__ sWm2 = (const u64*)sWm;   // [K][C/2] natural pairs

    // ---- Phase 1: mask for 2 adjacent pixels, packed along c ----
    const int pA = p0 + 2 * tid;
    const float* __restrict__ xp = xb + pA;

    u64 accA[K], accB[K];
#pragma unroll
    for (int k = 0; k < K; k++) {
        float bv = __ldg(&bm[k]);
        accA[k] = pack2(bv, 0.0f);   // bias seeded in lane0 (lanes = partial sums)
        accB[k] = pack2(bv, 0.0f);
    }

#pragma unroll 2
    for (int c = 0; c < C; c += 2) {
        float2 l0 = *(const float2*)(xp + (size_t)c * HW);        // ch c  : px A,B
        float2 l1 = *(const float2*)(xp + (size_t)(c + 1) * HW);  // ch c+1: px A,B
        u64 xA = pack2(l0.x, l1.x);   // pixel A, (c, c+1)
        u64 xB = pack2(l0.y, l1.y);   // pixel B, (c, c+1)
#pragma unroll
        for (int k = 0; k < K; k++) {
            u64 w = sWm2[(k * C + c) >> 1];   // (Wm[k,c], Wm[k,c+1]) LDS.64 broadcast
            fma2(accA[k], w, xA);
            fma2(accB[k], w, xB);
        }
    }

#pragma unroll
    for (int k = 0; k < K; k++) {
        float2 a = unpack2(accA[k]);
        float2 bq = unpack2(accB[k]);
        sMask[k * MP_T + 2 * tid]     = sigmoidf_(a.x + a.y);
        sMask[k * MP_T + 2 * tid + 1] = sigmoidf_(bq.x + bq.y);
    }
    __syncthreads();

    // ---- Phase 2: masked pooling, 2 channels / thread, packed along p ----
    const int c0 = tid;
    const int c1 = tid + MP_TPB;
    const float* __restrict__ xr0 = xb + (size_t)c0 * HW + p0;
    const float* __restrict__ xr1 = xb + (size_t)c1 * HW + p0;

    u64 s0[K], s1[K];
#pragma unroll
    for (int k = 0; k < K; k++) { s0[k] = 0ULL; s1[k] = 0ULL; }

#pragma unroll 2
    for (int p = 0; p < MP_T; p += 4) {
        float4 x0 = *(const float4*)(xr0 + p);
        float4 x1 = *(const float4*)(xr1 + p);
        u64 xa0 = pack2(x0.x, x0.y), xb0 = pack2(x0.z, x0.w);
        u64 xa1 = pack2(x1.x, x1.y), xb1 = pack2(x1.z, x1.w);
#pragma unroll
        for (int k = 0; k < K; k++) {
            u64 m0 = *(const u64*)&sMask[k * MP_T + p];      // mask pairs: natural
            u64 m1 = *(const u64*)&sMask[k * MP_T + p + 2];
            fma2(s0[k], m0, xa0); fma2(s0[k], m1, xb0);
            fma2(s1[k], m0, xa1); fma2(s1[k], m1, xb1);
        }
    }

#pragma unroll
    for (int k = 0; k < K; k++) {
        float2 a = unpack2(s0[k]);
        atomicAdd(&g_cf[((size_t)b * K + k) * C + c0], a.x + a.y);
        float2 bq = unpack2(s1[k]);
        atomicAdd(&g_cf[((size_t)b * K + k) * C + c1], bq.x + bq.y);
    }
}

// ---------------------------------------------------------------------------
// Kernel 2: filters[b,k,o] = sum_c Wf[k,o,c] * cf[b,k,c]/HW + bf[k,o]
// ---------------------------------------------------------------------------
__global__ __launch_bounds__(128) void filters_kernel(
    const float* __restrict__ Wf,
    const float* __restrict__ bf)
{
    __shared__ float scf[B * C];

    const int k   = blockIdx.x;
    const int tid = threadIdx.x;

    for (int i = tid; i < B * C; i += 128) {
        int bb = i / C, cc = i % C;
        scf[i] = g_cf[((size_t)bb * K + k) * C + cc] * INV_HW;
    }
    __syncthreads();

    const int o = blockIdx.y * 128 + tid;
    const float* __restrict__ wrow = Wf + ((size_t)k * C + o) * C;

    float acc[B];
#pragma unroll
    for (int bb = 0; bb < B; bb++) acc[bb] = 0.0f;

#pragma unroll 1
    for (int c = 0; c < C; c += 4) {
        float4 w = *(const float4*)(wrow + c);
#pragma unroll
        for (int bb = 0; bb < B; bb++) {
            float4 f = *(const float4*)&scf[bb * C + c];
            acc[bb] += w.x * f.x + w.y * f.y + w.z * f.z + w.w * f.w;
        }
    }

    float bias = __ldg(&bf[k * C + o]);
#pragma unroll
    for (int bb = 0; bb < B; bb++)
        g_filt[((size_t)bb * K + k) * C + o] = acc[bb] + bias;
}

// ---------------------------------------------------------------------------
// Kernel 3: pred[b,k,p] = sum_c filters[b,k,c] * x[b,c,p]   (FFMA2)
//   grid = (16, 8), block = 256, tile T=1024, 4 px / thread, packed along px
//   smem: sF2[K*C] duplicated (w,w) u64 pairs = 77824B
// ---------------------------------------------------------------------------
#define PR_TPB 256
#define PR_T   1024
#define PR_NT  (HW / PR_T)   // 16
#define PR_SMEM (K * C * 8)  // 77824

extern __shared__ float spr[];

__global__ __launch_bounds__(PR_TPB) void pred_kernel(
    const float* __restrict__ x,
    float* __restrict__ out)
{
    u64* sF2 = (u64*)spr;

    const int tid = threadIdx.x;
    const int b   = blockIdx.y;
    const int p0  = blockIdx.x * PR_T;
    const float* __restrict__ xb = x + (size_t)b * C * HW;
    const float* __restrict__ fb = g_filt + (size_t)b * K * C;

    for (int i = tid; i < K * C; i += PR_TPB) {
        float w = fb[i];
        sF2[i] = pack2(w, w);          // duplicated: lanes = pixels
    }
    __syncthreads();

    const int pp = p0 + tid * 4;
    const float* __restrict__ xp = xb + pp;

    u64 a01[K], a23[K];
#pragma unroll
    for (int k = 0; k < K; k++) { a01[k] = 0ULL; a23[k] = 0ULL; }

#pragma unroll 2
    for (int c = 0; c < C; c += 2) {
        float4 v0 = *(const float4*)(xp + (size_t)c * HW);
        float4 v1 = *(const float4*)(xp + (size_t)(c + 1) * HW);
        u64 xA0 = pack2(v0.x, v0.y), xB0 = pack2(v0.z, v0.w);
        u64 xA1 = pack2(v1.x, v1.y), xB1 = pack2(v1.z, v1.w);
#pragma unroll
        for (int k = 0; k < K; k++) {
            u64 w0 = sF2[k * C + c];
            u64 w1 = sF2[k * C + c + 1];
            fma2(a01[k], w0, xA0); fma2(a23[k], w0, xB0);
            fma2(a01[k], w1, xA1); fma2(a23[k], w1, xB1);
        }
    }

#pragma unroll
    for (int k = 0; k < K; k++) {
        float2 lo = unpack2(a01[k]);
        float2 hi = unpack2(a23[k]);
        float4 o = make_float4(lo.x, lo.y, hi.x, hi.y);
        *(float4*)&out[((size_t)b * K + k) * HW + pp] = o;
    }
}

// ---------------------------------------------------------------------------
extern "C" void kernel_launch(void* const* d_in, const int* in_sizes, int n_in,
                              void* d_out, int out_size)
{
    const float* x  = (const float*)d_in[0];
    const float* Wm = (const float*)d_in[1];
    const float* bm = (const float*)d_in[2];
    const float* Wf = (const float*)d_in[3];
    const float* bf = (const float*)d_in[4];
    float* out = (float*)d_out;

    static int attr_done = 0;
    cudaFuncSetAttribute(mask_pool_kernel,
                         cudaFuncAttributeMaxDynamicSharedMemorySize, MP_SMEM);
    cudaFuncSetAttribute(pred_kernel,
                         cudaFuncAttributeMaxDynamicSharedMemorySize, PR_SMEM);
    (void)attr_done;

    zero_cf_kernel<<<(B * K * C + 255) / 256, 256>>>();
    mask_pool_kernel<<<dim3(MP_NT, B), MP_TPB, MP_SMEM>>>(x, Wm, bm);
    filters_kernel<<<dim3(K, 4), 128>>>(Wf, bf);
    pred_kernel<<<dim3(PR_NT, B), PR_TPB, PR_SMEM>>>(x, out);
}

// round 7
// speedup vs baseline: 1.4036x; 1.4036x over previous
#include <cuda_runtime.h>
#include <cstdint>

#define B   8
#define C   512
#define K   19
#define KP  20              // padded K (2 groups of 10)
#define HW  16384
#define INV_HW (1.0f / 16384.0f)

typedef unsigned long long u64;

// scratch (__device__ globals: allocation-free rule)
__device__ float g_cf[B * K * C];      // class_feat accumulator
__device__ float g_filt[B * K * C];    // dynamic filters
__device__ float g_mask[B * K * HW];   // sigmoid mask, ~10 MB

// ---- packed f32x2 helpers ----
__device__ __forceinline__ u64 pack2(float lo, float hi) {
    u64 r; asm("mov.b64 %0, {%1, %2};" : "=l"(r) : "f"(lo), "f"(hi)); return r;
}
__device__ __forceinline__ void fma2(u64& d, u64 a, u64 b) {
    asm("fma.rn.f32x2 %0, %1, %2, %0;" : "+l"(d) : "l"(a), "l"(b));
}
__device__ __forceinline__ float2 unpack2(u64 v) {
    float2 f; asm("mov.b64 {%0, %1}, %2;" : "=f"(f.x), "=f"(f.y) : "l"(v)); return f;
}
__device__ __forceinline__ float sigmoidf_(float z) {
    return 1.0f / (1.0f + __expf(-z));
}

// ---------------------------------------------------------------------------
// Kernel 0: zero class_feat accumulator
// ---------------------------------------------------------------------------
__global__ void zero_cf_kernel() {
    int i = blockIdx.x * blockDim.x + threadIdx.x;
    if (i < B * K * C) g_cf[i] = 0.0f;
}

// ---------------------------------------------------------------------------
// Kernel 1: mask = sigmoid(Wm @ x + bm)  -> g_mask
//   block = 128 thr (64 px-quads x 2 k-groups), T = 256 px, grid = (64, B)
//   thread: 4 adjacent px, 10 k's, FFMA2 packed along pixels
// ---------------------------------------------------------------------------
#define MK_TPB 128
#define MK_T   256

__global__ __launch_bounds__(MK_TPB) void mask_kernel(
    const float* __restrict__ x,
    const float* __restrict__ Wm,
    const float* __restrict__ bm)
{
    __shared__ __align__(16) float sW[KP * C];   // 40960 B, row 19 zeroed

    const int tid = threadIdx.x;
    const int b   = blockIdx.y;
    const int p0  = blockIdx.x * MK_T;

    for (int i = tid; i < KP * C / 4; i += MK_TPB) {
        int k = i / (C / 4);
        float4 v = (k < K) ? ((const float4*)Wm)[i] : make_float4(0.f, 0.f, 0.f, 0.f);
        ((float4*)sW)[i] = v;
    }
    __syncthreads();

    const int quad = tid & 63;     // 0..63
    const int kg   = tid >> 6;     // 0 or 1
    const int k0   = kg * 10;
    const int px   = p0 + quad * 4;
    const float* __restrict__ xc = x + (size_t)b * C * HW + px;
    const float* __restrict__ sWk = sW + k0 * C;

    u64 accA[10], accB[10];
#pragma unroll
    for (int k = 0; k < 10; k++) { accA[k] = 0ULL; accB[k] = 0ULL; }

#pragma unroll 2
    for (int c = 0; c < C; c += 2) {
        float4 v0 = *(const float4*)(xc);
        float4 v1 = *(const float4*)(xc + HW);
        xc += 2 * HW;
        u64 xA0 = pack2(v0.x, v0.y), xB0 = pack2(v0.z, v0.w);
        u64 xA1 = pack2(v1.x, v1.y), xB1 = pack2(v1.z, v1.w);
#pragma unroll
        for (int k = 0; k < 10; k++) {
            float2 w = *(const float2*)&sWk[k * C + c];   // broadcast LDS.64
            u64 w0 = pack2(w.x, w.x);
            u64 w1 = pack2(w.y, w.y);
            fma2(accA[k], w0, xA0); fma2(accB[k], w0, xB0);
            fma2(accA[k], w1, xA1); fma2(accB[k], w1, xB1);
        }
    }

#pragma unroll
    for (int k = 0; k < 10; k++) {
        int kk = k0 + k;
        if (kk < K) {
            float bv = __ldg(&bm[kk]);
            float2 a = unpack2(accA[k]);
            float2 c2 = unpack2(accB[k]);
            float4 m;
            m.x = sigmoidf_(a.x + bv);
            m.y = sigmoidf_(a.y + bv);
            m.z = sigmoidf_(c2.x + bv);
            m.w = sigmoidf_(c2.y + bv);
            *(float4*)&g_mask[((size_t)b * K + kk) * HW + px] = m;
        }
    }
}

// ---------------------------------------------------------------------------
// Kernel 2: pooling  g_cf[b,k,c] += sum_p mask[b,k,p] * x[b,c,p]
//   block = 512 thr (256 ch-pairs x 2 k-groups), T = 512 px, grid = (32, B)
//   thread: 2 channels, 10 k's; mask pairs naturally packed along p
// ---------------------------------------------------------------------------
#define PL_TPB 512
#define PL_T   512

__global__ __launch_bounds__(PL_TPB) void pool_kernel(const float* __restrict__ x)
{
    __shared__ __align__(16) float sM[KP * PL_T];   // 40960 B, row 19 zeroed

    const int tid = threadIdx.x;
    const int b   = blockIdx.y;
    const int p0  = blockIdx.x * PL_T;

    {
        const float* mb = g_mask + (size_t)b * K * HW + p0;
        for (int i = tid; i < KP * (PL_T / 4); i += PL_TPB) {
            int k = i / (PL_T / 4);
            int j = i - k * (PL_T / 4);
            float4 v = (k < K) ? *(const float4*)(mb + (size_t)k * HW + j * 4)
                               : make_float4(0.f, 0.f, 0.f, 0.f);
            ((float4*)sM)[i] = v;
        }
    }
    __syncthreads();

    const int cp = tid & 255;     // channel pair id
    const int kg = tid >> 8;      // 0 or 1
    const int k0 = kg * 10;
    const int ch0 = cp * 2;
    const float* __restrict__ xp0 = x + (size_t)b * C * HW + (size_t)ch0 * HW + p0;
    const float* __restrict__ xp1 = xp0 + HW;
    const float* __restrict__ sMk = sM + k0 * PL_T;

    u64 a0[10], a1[10];
#pragma unroll
    for (int k = 0; k < 10; k++) { a0[k] = 0ULL; a1[k] = 0ULL; }

#pragma unroll 2
    for (int p = 0; p < PL_T; p += 4) {
        float4 v0 = *(const float4*)(xp0 + p);
        float4 v1 = *(const float4*)(xp1 + p);
        u64 x0A = pack2(v0.x, v0.y), x0B = pack2(v0.z, v0.w);
        u64 x1A = pack2(v1.x, v1.y), x1B = pack2(v1.z, v1.w);
#pragma unroll
        for (int k = 0; k < 10; k++) {
            u64 mA = *(const u64*)&sMk[k * PL_T + p];       // broadcast LDS
            u64 mB = *(const u64*)&sMk[k * PL_T + p + 2];
            fma2(a0[k], mA, x0A); fma2(a0[k], mB, x0B);
            fma2(a1[k], mA, x1A); fma2(a1[k], mB, x1B);
        }
    }

#pragma unroll
    for (int k = 0; k < 10; k++) {
        int kk = k0 + k;
        if (kk < K) {
            float2 s = unpack2(a0[k]);
            atomicAdd(&g_cf[((size_t)b * K + kk) * C + ch0], s.x + s.y);
            float2 t = unpack2(a1[k]);
            atomicAdd(&g_cf[((size_t)b * K + kk) * C + ch0 + 1], t.x + t.y);
        }
    }
}

// ---------------------------------------------------------------------------
// Kernel 3: filters[b,k,o] = sum_c Wf[k,o,c] * cf[b,k,c]/HW + bf[k,o]
// ---------------------------------------------------------------------------
__global__ __launch_bounds__(128) void filters_kernel(
    const float* __restrict__ Wf,
    const float* __restrict__ bf)
{
    __shared__ float scf[B * C];

    const int k   = blockIdx.x;
    const int tid = threadIdx.x;

    for (int i = tid; i < B * C; i += 128) {
        int bb = i / C, cc = i % C;
        scf[i] = g_cf[((size_t)bb * K + k) * C + cc] * INV_HW;
    }
    __syncthreads();

    const int o = blockIdx.y * 128 + tid;
    const float* __restrict__ wrow = Wf + ((size_t)k * C + o) * C;

    float acc[B];
#pragma unroll
    for (int bb = 0; bb < B; bb++) acc[bb] = 0.0f;

#pragma unroll 1
    for (int c = 0; c < C; c += 4) {
        float4 w = *(const float4*)(wrow + c);
#pragma unroll
        for (int bb = 0; bb < B; bb++) {
            float4 f = *(const float4*)&scf[bb * C + c];
            acc[bb] += w.x * f.x + w.y * f.y + w.z * f.z + w.w * f.w;
        }
    }

    float bias = __ldg(&bf[k * C + o]);
#pragma unroll
    for (int bb = 0; bb < B; bb++)
        g_filt[((size_t)bb * K + k) * C + o] = acc[bb] + bias;
}

// ---------------------------------------------------------------------------
// Kernel 4: pred[b,k,p] = sum_c filters[b,k,c] * x[b,c,p]
//   same structure as mask_kernel (no sigmoid), writes d_out
// ---------------------------------------------------------------------------
#define PR_TPB 128
#define PR_T   256

__global__ __launch_bounds__(PR_TPB) void pred_kernel(
    const float* __restrict__ x,
    float* __restrict__ out)
{
    __shared__ __align__(16) float sF[KP * C];   // 40960 B, row 19 zeroed

    const int tid = threadIdx.x;
    const int b   = blockIdx.y;
    const int p0  = blockIdx.x * PR_T;

    {
        const float* fb = g_filt + (size_t)b * K * C;
        for (int i = tid; i < KP * C / 4; i += PR_TPB) {
            int k = i / (C / 4);
            float4 v = (k < K) ? ((const float4*)fb)[i] : make_float4(0.f, 0.f, 0.f, 0.f);
            ((float4*)sF)[i] = v;
        }
    }
    __syncthreads();

    const int quad = tid & 63;
    const int kg   = tid >> 6;
    const int k0   = kg * 10;
    const int px   = p0 + quad * 4;
    const float* __restrict__ xc = x + (size_t)b * C * HW + px;
    const float* __restrict__ sFk = sF + k0 * C;

    u64 accA[10], accB[10];
#pragma unroll
    for (int k = 0; k < 10; k++) { accA[k] = 0ULL; accB[k] = 0ULL; }

#pragma unroll 2
    for (int c = 0; c < C; c += 2) {
        float4 v0 = *(const float4*)(xc);
        float4 v1 = *(const float4*)(xc + HW);
        xc += 2 * HW;
        u64 xA0 = pack2(v0.x, v0.y), xB0 = pack2(v0.z, v0.w);
        u64 xA1 = pack2(v1.x, v1.y), xB1 = pack2(v1.z, v1.w);
#pragma unroll
        for (int k = 0; k < 10; k++) {
            float2 w = *(const float2*)&sFk[k * C + c];
            u64 w0 = pack2(w.x, w.x);
            u64 w1 = pack2(w.y, w.y);
            fma2(accA[k], w0, xA0); fma2(accB[k], w0, xB0);
            fma2(accA[k], w1, xA1); fma2(accB[k], w1, xB1);
        }
    }

#pragma unroll
    for (int k = 0; k < 10; k++) {
        int kk = k0 + k;
        if (kk < K) {
            float2 a = unpack2(accA[k]);
            float2 c2 = unpack2(accB[k]);
            float4 o = make_float4(a.x, a.y, c2.x, c2.y);
            *(float4*)&out[((size_t)b * K + kk) * HW + px] = o;
        }
    }
}

// ---------------------------------------------------------------------------
extern "C" void kernel_launch(void* const* d_in, const int* in_sizes, int n_in,
                              void* d_out, int out_size)
{
    const float* x  = (const float*)d_in[0];
    const float* Wm = (const float*)d_in[1];
    const float* bm = (const float*)d_in[2];
    const float* Wf = (const float*)d_in[3];
    const float* bf = (const float*)d_in[4];
    float* out = (float*)d_out;

    zero_cf_kernel<<<(B * K * C + 255) / 256, 256>>>();
    mask_kernel<<<dim3(HW / MK_T, B), MK_TPB>>>(x, Wm, bm);
    pool_kernel<<<dim3(HW / PL_T, B), PL_TPB>>>(x);
    filters_kernel<<<dim3(K, 4), 128>>>(Wf, bf);
    pred_kernel<<<dim3(HW / PR_T, B), PR_TPB>>>(x, out);
}